// round 7
// baseline (speedup 1.0000x reference)
#include <cuda_runtime.h>
#include <cstdint>
#include <math.h>

#define E_EDGES 640000
#define N_NODES 10000
#define D 128
#define H 4
#define NCOMB 1024
#define PHALF 512

// ---------------- scratch ---------------------------------------------------
__device__ __align__(16) float    g_Wcomb[NCOMB * D];            // tf32-rounded
__device__ __align__(16) float    g_W2r[D * D];                  // tf32-rounded W2
__device__ __align__(16) float    g_Y[(size_t)E_EDGES * PHALF];  // p-half (1.31 GB)
__device__ float    g_att[E_EDGES * H];
__device__ unsigned g_m[N_NODES * H];
__device__ float    g_s[N_NODES * H];

// ---------------- helpers ---------------------------------------------------
__device__ __forceinline__ uint32_t smem_u32(const void* p) {
    uint32_t a;
    asm("{ .reg .u64 t; cvta.to.shared.u64 t, %1; cvt.u32.u64 %0, t; }" : "=r"(a) : "l"(p));
    return a;
}
__device__ __forceinline__ uint32_t tf32r(float x) {
    uint32_t r; asm("cvt.rna.tf32.f32 %0, %1;" : "=r"(r) : "f"(x)); return r;
}
__device__ __forceinline__ void ldsm4(uint32_t* r, uint32_t addr) {
    asm volatile("ldmatrix.sync.aligned.m8n8.x4.shared.b16 {%0,%1,%2,%3}, [%4];"
                 : "=r"(r[0]), "=r"(r[1]), "=r"(r[2]), "=r"(r[3]) : "r"(addr));
}
__device__ __forceinline__ void mma_tf32(float* d, const uint32_t* a, const uint32_t* b) {
    asm volatile("mma.sync.aligned.m16n8k8.row.col.f32.tf32.tf32.f32 "
                 "{%0,%1,%2,%3}, {%4,%5,%6,%7}, {%8,%9}, {%0,%1,%2,%3};"
                 : "+f"(d[0]), "+f"(d[1]), "+f"(d[2]), "+f"(d[3])
                 : "r"(a[0]), "r"(a[1]), "r"(a[2]), "r"(a[3]), "r"(b[0]), "r"(b[1]));
}
#define CP_ASYNC16(dst, src) \
    asm volatile("cp.async.cg.shared.global [%0], [%1], 16;" :: "r"(dst), "l"(src))
#define CP_COMMIT() asm volatile("cp.async.commit_group;" ::: "memory")
#define CP_WAIT0()  asm volatile("cp.async.wait_group 0;" ::: "memory")

__device__ __forceinline__ unsigned encodeF(float x) {
    unsigned u = __float_as_uint(x);
    return (u & 0x80000000u) ? ~u : (u | 0x80000000u);
}
__device__ __forceinline__ float decodeF(unsigned e) {
    unsigned u = (e & 0x80000000u) ? (e ^ 0x80000000u) : ~e;
    return __uint_as_float(u);
}

// ---------------- K0: build combined weights (tf32-rounded) ----------------
__global__ void k_build(const float* __restrict__ Wq, const float* __restrict__ Wk,
                        const float* __restrict__ Wv, const float* __restrict__ W1,
                        const float* __restrict__ W2) {
    int n = blockIdx.x;
    int f = threadIdx.x;
    if (n < NCOMB) {
        float acc = 0.f;
        if (n < H * D) {
            int h = n >> 7, g = n & 127;
            const float* wq = Wq + h * D * D;
            const float* wk = Wk + h * D * D;
            for (int d = 0; d < D; d++) acc += wq[d * D + f] * wk[d * D + g];
        } else {
            int m2 = n - H * D;
            int h = m2 >> 7, i = m2 & 127;
            const float* wv = Wv + h * D * D;
            for (int d = 0; d < D; d++) acc += W1[i * D + d] * wv[d * D + f];
        }
        g_Wcomb[n * D + f] = __uint_as_float(tf32r(acc));
    } else {
        int i = n - NCOMB;
        g_W2r[i * D + f] = __uint_as_float(tf32r(W2[i * D + f]));
    }
}

// ---------------- K1: reset segment buffers --------------------------------
__global__ void k_init() {
    int i = blockIdx.x * 256 + threadIdx.x;
    if (i < N_NODES * H) { g_m[i] = 0u; g_s[i] = 0.f; }
}

// ---------------- dummy (profiler alignment) --------------------------------
__global__ void k_nop() {}

// ---------------- K2: tf32 mma GEMM, M=256 x N=64 tiles, 512 thr -----------
// smem tile layout: row stride 512B, 16B chunks XOR-swizzled:
//   addr(row, k) = base + row*512 + (((k>>2) ^ (row&7))<<4) + (k&3)*4
#define SM_ATT 0                   // 256 floats
#define SM_ROW 1024                // 256 ints
#define SM_Z   2048                // 256 rows * 512B = 128KB
#define SM_W0  (2048 + 131072)     // 64 rows * 512B = 32KB
#define SM_W1  (2048 + 131072 + 32768)
#define SMEM_SZ (2048 + 131072 + 65536)   // 194.5KB

__global__ void __launch_bounds__(512, 1) k_mma(const float* __restrict__ Z,
                                                const int* __restrict__ row) {
    extern __shared__ char smem[];
    float* attbuf = (float*)(smem + SM_ATT);
    int* rs = (int*)(smem + SM_ROW);
    const int tid = threadIdx.x;
    const int lane = tid & 31, wid = tid >> 5;        // 16 warps
    const int warpM = wid >> 1, warpN = wid & 1;      // 8 x 2
    const int m_base = warpM * 32, n_base = warpN * 32;
    const int e0 = blockIdx.x * 256;

    const uint32_t zbase = smem_u32(smem + SM_Z);
    const uint32_t wbase[2] = { smem_u32(smem + SM_W0), smem_u32(smem + SM_W1) };

    if (tid < 256) rs[tid] = row[e0 + tid];

    // ---- Z tile: 256 x 128, tf32-rounded, swizzled ----
#pragma unroll
    for (int it = 0; it < 16; it++) {
        int i = it * 512 + tid;
        int r = i >> 5, c = i & 31;
        float4 v = *(const float4*)&Z[(size_t)(e0 + r) * D + c * 4];
        uint4 w = { tf32r(v.x), tf32r(v.y), tf32r(v.z), tf32r(v.w) };
        *(uint4*)(smem + SM_Z + r * 512 + (((uint32_t)c ^ (r & 7)) << 4)) = w;
    }

    // ---- prefetch W n-tile 0 (64 rows) ----
#pragma unroll
    for (int it = 0; it < 4; it++) {
        int i = it * 512 + tid;
        int r = i >> 5, c = i & 31;
        CP_ASYNC16(wbase[0] + r * 512 + (((uint32_t)c ^ (r & 7)) << 4),
                   &g_Wcomb[(size_t)r * D + c * 4]);
    }
    CP_COMMIT();

    const int g8 = lane >> 3, l8 = lane & 7;
    uint32_t arow[2], asw[2];
#pragma unroll
    for (int f = 0; f < 2; f++) {
        int r = m_base + f * 16 + (g8 & 1) * 8 + l8;
        arow[f] = (uint32_t)r * 512;
        asw[f] = (uint32_t)(r & 7);
    }
    const uint32_t ack = (uint32_t)(g8 >> 1);
    uint32_t brow[2], bsw[2];
#pragma unroll
    for (int q = 0; q < 2; q++) {
        int r = n_base + q * 16 + (g8 >> 1) * 8 + l8;
        brow[q] = (uint32_t)r * 512;
        bsw[q] = (uint32_t)(r & 7);
    }
    const uint32_t bck = (uint32_t)(g8 & 1);

    const int crow = m_base + (lane >> 2);
    const int ccol = n_base + (lane & 3) * 2;   // within 64-wide n-tile

    for (int nt = 0; nt < 16; nt++) {
        const int buf = nt & 1;
        CP_WAIT0();
        __syncthreads();
        if (nt < 15) {
#pragma unroll
            for (int it = 0; it < 4; it++) {
                int i = it * 512 + tid;
                int r = i >> 5, c = i & 31;
                CP_ASYNC16(wbase[buf ^ 1] + r * 512 + (((uint32_t)c ^ (r & 7)) << 4),
                           &g_Wcomb[(size_t)(nt + 1) * 64 * D + (size_t)r * D + c * 4]);
            }
            CP_COMMIT();
        }

        float acc[2][4][4];
#pragma unroll
        for (int f = 0; f < 2; f++)
#pragma unroll
            for (int j = 0; j < 4; j++)
#pragma unroll
                for (int r = 0; r < 4; r++) acc[f][j][r] = 0.f;

        const uint32_t wb = wbase[buf];
#pragma unroll
        for (int ks = 0; ks < 16; ks++) {
            const uint32_t kk = (uint32_t)(ks * 2);
            uint32_t afr[2][4];
#pragma unroll
            for (int f = 0; f < 2; f++)
                ldsm4(afr[f], zbase + arow[f] + (((kk + ack) ^ asw[f]) << 4));
            uint32_t bfr[4][2];
#pragma unroll
            for (int q = 0; q < 2; q++) {
                uint32_t t4[4];
                ldsm4(t4, wb + brow[q] + (((kk + bck) ^ bsw[q]) << 4));
                bfr[2 * q][0] = t4[0]; bfr[2 * q][1] = t4[1];
                bfr[2 * q + 1][0] = t4[2]; bfr[2 * q + 1][1] = t4[3];
            }
#pragma unroll
            for (int f = 0; f < 2; f++)
#pragma unroll
                for (int j = 0; j < 4; j++)
                    mma_tf32(acc[f][j], afr[f], bfr[j]);
        }

        if (nt < 8) {
            // ---- att partial epilogue: head h = nt>>1, feature base (nt&1)*64
            const int h = nt >> 1;
            if ((nt & 1) == 0) {
                if (tid < 256) attbuf[tid] = 0.f;
                __syncthreads();
            }
            float part[2][2] = {{0.f, 0.f}, {0.f, 0.f}};
#pragma unroll
            for (int f = 0; f < 2; f++)
#pragma unroll
                for (int j = 0; j < 4; j++) {
                    int zcol = (nt & 1) * 64 + ccol + j * 8;
                    uint32_t coff = (((uint32_t)(zcol >> 2)) << 4) + (zcol & 3) * 4;
#pragma unroll
                    for (int r8 = 0; r8 < 2; r8++) {
                        int rr = crow + f * 16 + r8 * 8;
                        uint32_t sw = ((uint32_t)(rr & 7)) << 4;
                        float2 z = *(const float2*)(smem + SM_Z + rr * 512 + (coff ^ sw));
                        part[f][r8] += acc[f][j][r8 * 2] * z.x + acc[f][j][r8 * 2 + 1] * z.y;
                    }
                }
#pragma unroll
            for (int f = 0; f < 2; f++)
#pragma unroll
                for (int r8 = 0; r8 < 2; r8++) {
                    float p = part[f][r8];
                    p += __shfl_xor_sync(0xFFFFFFFFu, p, 1);
                    p += __shfl_xor_sync(0xFFFFFFFFu, p, 2);
                    if ((lane & 3) == 0)
                        atomicAdd(&attbuf[crow + f * 16 + r8 * 8], p);
                }
            if (nt & 1) {
                __syncthreads();
                if (tid < 256) {
                    float v = 0.08838834764831845f * attbuf[tid];
                    g_att[(size_t)(e0 + tid) * H + h] = v;
                    atomicMax(&g_m[rs[tid] * H + h], encodeF(v));
                }
            }
        } else {
            // ---- p-half store ----
            const int colb = (nt - 8) * 64 + ccol;
#pragma unroll
            for (int f = 0; f < 2; f++) {
                int r0 = crow + f * 16;
#pragma unroll
                for (int j = 0; j < 4; j++) {
                    *(float2*)&g_Y[(size_t)(e0 + r0) * PHALF + colb + j * 8] =
                        make_float2(acc[f][j][0], acc[f][j][1]);
                    *(float2*)&g_Y[(size_t)(e0 + r0 + 8) * PHALF + colb + j * 8] =
                        make_float2(acc[f][j][2], acc[f][j][3]);
                }
            }
        }
    }
}

// ---------------- K4: exp + segment sum ------------------------------------
__global__ void k_exp(const int* __restrict__ row) {
    int i = blockIdx.x * 256 + threadIdx.x;
    if (i >= E_EDGES * H) return;
    int e = i >> 2, h = i & 3;
    int rw = row[e];
    float m = decodeF(g_m[rw * H + h]);
    float ev = __expf(g_att[i] - m);
    g_att[i] = ev;
    atomicAdd(&g_s[rw * H + h], ev);
}

// ---------------- K5: final, 64-edge tiles, 128 thr, 2 CTAs/SM -------------
#define SMF_WS  0                 // 256 floats
#define SMF_B1  1024
#define SMF_B2  1536
#define SMF_H1  2048              // 64 rows * 512B = 32KB
#define SMF_W2  (2048 + 32768)    // 128 rows * 512B = 64KB
#define SMEMF_SZ (2048 + 32768 + 65536)   // 98KB

__global__ void __launch_bounds__(128, 2) k_final(const int* __restrict__ row,
                                                  const float* __restrict__ b1,
                                                  const float* __restrict__ b2,
                                                  float* __restrict__ out) {
    extern __shared__ char smem[];
    float* ws  = (float*)(smem + SMF_WS);
    float* b1s = (float*)(smem + SMF_B1);
    float* b2s = (float*)(smem + SMF_B2);
    const int tid = threadIdx.x;
    const int lane = tid & 31, wid = tid >> 5;   // 4 warps
    const int e0 = blockIdx.x * 64;
    const uint32_t h1base = smem_u32(smem + SMF_H1);
    const uint32_t w2base = smem_u32(smem + SMF_W2);

    // prefetch full W2 tile (128 rows)
#pragma unroll
    for (int it = 0; it < 32; it++) {
        int i = it * 128 + tid;
        int r = i >> 5, c = i & 31;
        CP_ASYNC16(w2base + r * 512 + (((uint32_t)c ^ (r & 7)) << 4),
                   &g_W2r[(size_t)r * D + c * 4]);
    }
    CP_COMMIT();

    if (tid < 128) { b1s[tid] = b1[tid]; b2s[tid] = b2[tid]; }
#pragma unroll
    for (int it = 0; it < 2; it++) {
        int idx = it * 128 + tid;
        int e = e0 + (idx >> 2), h = idx & 3;
        ws[idx] = g_att[(size_t)e * H + h] / g_s[row[e] * H + h];
    }
    __syncthreads();

    // h1 = SiLU(sum_h w*p + b1), tf32-rounded into swizzled smem
#pragma unroll
    for (int it = 0; it < 64; it++) {
        int idx = it * 128 + tid;
        int m = idx >> 7, c = idx & 127;
        const float* yp = g_Y + (size_t)(e0 + m) * PHALF + c;
        const float4 w4 = *(const float4*)&ws[m * 4];
        float pre = b1s[c] + w4.x * yp[0] + w4.y * yp[128] + w4.z * yp[256] + w4.w * yp[384];
        float h1 = pre / (1.f + __expf(-pre));
        *(uint32_t*)(smem + SMF_H1 + m * 512 + ((((uint32_t)(c >> 2)) ^ (m & 7)) << 4)
                     + (c & 3) * 4) = tf32r(h1);
    }
    CP_WAIT0();
    __syncthreads();

    // mma: out = h1(64x128) @ W2^T(128x128); warp covers all M=64, n32 slice
    const int n_base = wid * 32;
    const int g8 = lane >> 3, l8 = lane & 7;
    uint32_t arow[4], asw[4];
#pragma unroll
    for (int f = 0; f < 4; f++) {
        int r = f * 16 + (g8 & 1) * 8 + l8;
        arow[f] = (uint32_t)r * 512;
        asw[f] = (uint32_t)(r & 7);
    }
    const uint32_t ack = (uint32_t)(g8 >> 1);
    uint32_t brow[2], bsw[2];
#pragma unroll
    for (int q = 0; q < 2; q++) {
        int r = n_base + q * 16 + (g8 >> 1) * 8 + l8;
        brow[q] = (uint32_t)r * 512;
        bsw[q] = (uint32_t)(r & 7);
    }
    const uint32_t bck = (uint32_t)(g8 & 1);

    float acc[4][4][4];
#pragma unroll
    for (int f = 0; f < 4; f++)
#pragma unroll
        for (int j = 0; j < 4; j++)
#pragma unroll
            for (int r = 0; r < 4; r++) acc[f][j][r] = 0.f;

#pragma unroll
    for (int ks = 0; ks < 16; ks++) {
        const uint32_t kk = (uint32_t)(ks * 2);
        uint32_t afr[4][4];
#pragma unroll
        for (int f = 0; f < 4; f++)
            ldsm4(afr[f], h1base + arow[f] + (((kk + ack) ^ asw[f]) << 4));
        uint32_t bfr[4][2];
#pragma unroll
        for (int q = 0; q < 2; q++) {
            uint32_t t4[4];
            ldsm4(t4, w2base + brow[q] + (((kk + bck) ^ bsw[q]) << 4));
            bfr[2 * q][0] = t4[0]; bfr[2 * q][1] = t4[1];
            bfr[2 * q + 1][0] = t4[2]; bfr[2 * q + 1][1] = t4[3];
        }
#pragma unroll
        for (int f = 0; f < 4; f++)
#pragma unroll
            for (int j = 0; j < 4; j++)
                mma_tf32(acc[f][j], afr[f], bfr[j]);
    }

    const int ccol = n_base + (lane & 3) * 2;
#pragma unroll
    for (int f = 0; f < 4; f++) {
        int r0 = e0 + f * 16 + (lane >> 2);
#pragma unroll
        for (int j = 0; j < 4; j++) {
            int col = ccol + j * 8;
            float bx = b2s[col], by = b2s[col + 1];
            *(float2*)&out[(size_t)r0 * D + col] =
                make_float2(acc[f][j][0] + bx, acc[f][j][1] + by);
            *(float2*)&out[(size_t)(r0 + 8) * D + col] =
                make_float2(acc[f][j][2] + bx, acc[f][j][3] + by);
        }
    }
}

// ---------------- launch ----------------------------------------------------
extern "C" void kernel_launch(void* const* d_in, const int* in_sizes, int n_in,
                              void* d_out, int out_size) {
    const float* Z     = (const float*)d_in[0];
    const int*   edges = (const int*)  d_in[1];
    const float* Wq    = (const float*)d_in[2];
    const float* Wk    = (const float*)d_in[3];
    const float* Wv    = (const float*)d_in[4];
    const float* W1    = (const float*)d_in[5];
    const float* b1    = (const float*)d_in[6];
    const float* W2    = (const float*)d_in[7];
    const float* b2    = (const float*)d_in[8];
    float* out = (float*)d_out;
    const int* row = edges;

    cudaFuncSetAttribute(k_mma, cudaFuncAttributeMaxDynamicSharedMemorySize, SMEM_SZ);
    cudaFuncSetAttribute(k_final, cudaFuncAttributeMaxDynamicSharedMemorySize, SMEMF_SZ);

    k_build<<<NCOMB + D, D>>>(Wq, Wk, Wv, W1, W2);
    k_init<<<(N_NODES * H + 255) / 256, 256>>>();
    k_nop<<<1, 1>>>();   // aligns ncu capture (launch idx 3) onto k_mma
    k_mma<<<E_EDGES / 256, 512, SMEM_SZ>>>(Z, row);
    k_exp<<<(E_EDGES * H + 255) / 256, 256>>>(row);
    k_final<<<E_EDGES / 64, 128, SMEMF_SZ>>>(row, b1, b2, out);
}

// round 8
// speedup vs baseline: 1.2252x; 1.2252x over previous
#include <cuda_runtime.h>
#include <cstdint>
#include <math.h>

#define E_EDGES 640000
#define N_NODES 10000
#define D 128
#define H 4
#define NCOMB 1024
#define PHALF 512

// ---------------- scratch ---------------------------------------------------
__device__ __align__(16) float    g_Wcomb[NCOMB * D];            // tf32-rounded
__device__ __align__(16) float    g_W2r[D * D];                  // tf32-rounded W2
__device__ __align__(16) float    g_Y[(size_t)E_EDGES * PHALF];  // p-half (1.31 GB)
__device__ float    g_att[E_EDGES * H];
__device__ unsigned g_m[N_NODES * H];
__device__ float    g_s[N_NODES * H];

// ---------------- helpers ---------------------------------------------------
__device__ __forceinline__ uint32_t smem_u32(const void* p) {
    uint32_t a;
    asm("{ .reg .u64 t; cvta.to.shared.u64 t, %1; cvt.u32.u64 %0, t; }" : "=r"(a) : "l"(p));
    return a;
}
__device__ __forceinline__ uint32_t tf32r(float x) {
    uint32_t r; asm("cvt.rna.tf32.f32 %0, %1;" : "=r"(r) : "f"(x)); return r;
}
__device__ __forceinline__ void ldsm4(uint32_t* r, uint32_t addr) {
    asm volatile("ldmatrix.sync.aligned.m8n8.x4.shared.b16 {%0,%1,%2,%3}, [%4];"
                 : "=r"(r[0]), "=r"(r[1]), "=r"(r[2]), "=r"(r[3]) : "r"(addr));
}
__device__ __forceinline__ void mma_tf32(float* d, const uint32_t* a, const uint32_t* b) {
    asm volatile("mma.sync.aligned.m16n8k8.row.col.f32.tf32.tf32.f32 "
                 "{%0,%1,%2,%3}, {%4,%5,%6,%7}, {%8,%9}, {%0,%1,%2,%3};"
                 : "+f"(d[0]), "+f"(d[1]), "+f"(d[2]), "+f"(d[3])
                 : "r"(a[0]), "r"(a[1]), "r"(a[2]), "r"(a[3]), "r"(b[0]), "r"(b[1]));
}
#define CP_ASYNC16(dst, src) \
    asm volatile("cp.async.cg.shared.global [%0], [%1], 16;" :: "r"(dst), "l"(src))
#define CP_COMMIT() asm volatile("cp.async.commit_group;" ::: "memory")
#define CP_WAIT0()  asm volatile("cp.async.wait_group 0;" ::: "memory")

__device__ __forceinline__ unsigned encodeF(float x) {
    unsigned u = __float_as_uint(x);
    return (u & 0x80000000u) ? ~u : (u | 0x80000000u);
}
__device__ __forceinline__ float decodeF(unsigned e) {
    unsigned u = (e & 0x80000000u) ? (e ^ 0x80000000u) : ~e;
    return __uint_as_float(u);
}

// ---------------- K0: build combined weights (tf32-rounded) ----------------
__global__ void k_build(const float* __restrict__ Wq, const float* __restrict__ Wk,
                        const float* __restrict__ Wv, const float* __restrict__ W1,
                        const float* __restrict__ W2) {
    int n = blockIdx.x;
    int f = threadIdx.x;
    if (n < NCOMB) {
        float acc = 0.f;
        if (n < H * D) {
            int h = n >> 7, g = n & 127;
            const float* wq = Wq + h * D * D;
            const float* wk = Wk + h * D * D;
            for (int d = 0; d < D; d++) acc += wq[d * D + f] * wk[d * D + g];
        } else {
            int m2 = n - H * D;
            int h = m2 >> 7, i = m2 & 127;
            const float* wv = Wv + h * D * D;
            for (int d = 0; d < D; d++) acc += W1[i * D + d] * wv[d * D + f];
        }
        g_Wcomb[n * D + f] = __uint_as_float(tf32r(acc));
    } else {
        int i = n - NCOMB;
        g_W2r[i * D + f] = __uint_as_float(tf32r(W2[i * D + f]));
    }
}

// ---------------- K1: reset segment buffers --------------------------------
__global__ void k_init() {
    int i = blockIdx.x * 256 + threadIdx.x;
    if (i < N_NODES * H) { g_m[i] = 0u; g_s[i] = 0.f; }
}

// ---------------- dummy (profiler alignment) --------------------------------
__global__ void k_nop() {}

// ---------------- K2: tf32 mma GEMM, M=128 x N=32 tiles, 2 CTAs/SM ---------
// smem tile layout: row stride 512B, 16B chunks XOR-swizzled:
//   addr(row, k) = base + row*512 + (((k>>2) ^ (row&7))<<4) + (k&3)*4
#define SM_ATT 0                   // 128 floats
#define SM_ROW 512                 // 128 ints
#define SM_Z   1024                // 128 rows * 512B = 64KB
#define SM_W0  (1024 + 65536)      // 32 rows * 512B = 16KB
#define SM_W1  (1024 + 65536 + 16384)
#define SMEM_SZ (1024 + 65536 + 32768)   // 98304+1024 = 97.25KB

__global__ void __launch_bounds__(256, 2) k_mma(const float* __restrict__ Z,
                                                const int* __restrict__ row) {
    extern __shared__ char smem[];
    float* attbuf = (float*)(smem + SM_ATT);
    int* rs = (int*)(smem + SM_ROW);
    const int tid = threadIdx.x;
    const int lane = tid & 31, wid = tid >> 5;       // 8 warps
    const int warpM = wid & 3, warpN = wid >> 2;     // 4M x 2N
    const int m_base = warpM * 32, n_base = warpN * 16;
    const int e0 = blockIdx.x * 128;

    const uint32_t zbase = smem_u32(smem + SM_Z);
    const uint32_t wbase[2] = { smem_u32(smem + SM_W0), smem_u32(smem + SM_W1) };

    if (tid < 128) rs[tid] = row[e0 + tid];

    // ---- Z tile: 128 x 128, tf32-rounded, swizzled ----
#pragma unroll
    for (int it = 0; it < 16; it++) {
        int i = it * 256 + tid;
        int r = i >> 5, c = i & 31;
        float4 v = *(const float4*)&Z[(size_t)(e0 + r) * D + c * 4];
        uint4 w = { tf32r(v.x), tf32r(v.y), tf32r(v.z), tf32r(v.w) };
        *(uint4*)(smem + SM_Z + r * 512 + (((uint32_t)c ^ (r & 7)) << 4)) = w;
    }

    // ---- prefetch W n-tile 0 (32 rows) ----
#pragma unroll
    for (int it = 0; it < 4; it++) {
        int i = it * 256 + tid;
        int r = i >> 5, c = i & 31;
        CP_ASYNC16(wbase[0] + r * 512 + (((uint32_t)c ^ (r & 7)) << 4),
                   &g_Wcomb[(size_t)r * D + c * 4]);
    }
    CP_COMMIT();

    const int g8 = lane >> 3, l8 = lane & 7;
    uint32_t arow[2], asw[2];
#pragma unroll
    for (int f = 0; f < 2; f++) {
        int r = m_base + f * 16 + (g8 & 1) * 8 + l8;
        arow[f] = (uint32_t)r * 512;
        asw[f] = (uint32_t)(r & 7);
    }
    const uint32_t ack = (uint32_t)(g8 >> 1);
    uint32_t brow, bsw;
    {
        int r = n_base + (g8 >> 1) * 8 + l8;
        brow = (uint32_t)r * 512;
        bsw = (uint32_t)(r & 7);
    }
    const uint32_t bck = (uint32_t)(g8 & 1);

    const int crow = m_base + (lane >> 2);
    const int ccol = n_base + (lane & 3) * 2;   // within 32-wide n-tile

    for (int nt = 0; nt < 32; nt++) {
        const int buf = nt & 1;
        CP_WAIT0();
        __syncthreads();
        if (nt < 31) {
#pragma unroll
            for (int it = 0; it < 4; it++) {
                int i = it * 256 + tid;
                int r = i >> 5, c = i & 31;
                CP_ASYNC16(wbase[buf ^ 1] + r * 512 + (((uint32_t)c ^ (r & 7)) << 4),
                           &g_Wcomb[(size_t)(nt + 1) * 32 * D + (size_t)r * D + c * 4]);
            }
            CP_COMMIT();
        }

        float acc[2][2][4];
#pragma unroll
        for (int f = 0; f < 2; f++)
#pragma unroll
            for (int j = 0; j < 2; j++)
#pragma unroll
                for (int r = 0; r < 4; r++) acc[f][j][r] = 0.f;

        const uint32_t wb = wbase[buf];
#pragma unroll
        for (int ks = 0; ks < 16; ks++) {
            const uint32_t kk = (uint32_t)(ks * 2);
            uint32_t afr[2][4];
#pragma unroll
            for (int f = 0; f < 2; f++)
                ldsm4(afr[f], zbase + arow[f] + (((kk + ack) ^ asw[f]) << 4));
            uint32_t bfr[2][2];
            {
                uint32_t t4[4];
                ldsm4(t4, wb + brow + (((kk + bck) ^ bsw) << 4));
                bfr[0][0] = t4[0]; bfr[0][1] = t4[1];
                bfr[1][0] = t4[2]; bfr[1][1] = t4[3];
            }
#pragma unroll
            for (int f = 0; f < 2; f++)
#pragma unroll
                for (int j = 0; j < 2; j++)
                    mma_tf32(acc[f][j], afr[f], bfr[j]);
        }

        if (nt < 16) {
            // ---- att partial epilogue: head h = nt>>2, feature base (nt&3)*32
            const int h = nt >> 2;
            if ((nt & 3) == 0) {
                if (tid < 128) attbuf[tid] = 0.f;
                __syncthreads();
            }
            float part[2][2] = {{0.f, 0.f}, {0.f, 0.f}};
#pragma unroll
            for (int f = 0; f < 2; f++)
#pragma unroll
                for (int j = 0; j < 2; j++) {
                    int zcol = (nt & 3) * 32 + ccol + j * 8;
                    uint32_t coff = (((uint32_t)(zcol >> 2)) << 4) + (zcol & 3) * 4;
#pragma unroll
                    for (int r8 = 0; r8 < 2; r8++) {
                        int rr = crow + f * 16 + r8 * 8;
                        uint32_t sw = ((uint32_t)(rr & 7)) << 4;
                        float2 z = *(const float2*)(smem + SM_Z + rr * 512 + (coff ^ sw));
                        part[f][r8] += acc[f][j][r8 * 2] * z.x + acc[f][j][r8 * 2 + 1] * z.y;
                    }
                }
#pragma unroll
            for (int f = 0; f < 2; f++)
#pragma unroll
                for (int r8 = 0; r8 < 2; r8++) {
                    float p = part[f][r8];
                    p += __shfl_xor_sync(0xFFFFFFFFu, p, 1);
                    p += __shfl_xor_sync(0xFFFFFFFFu, p, 2);
                    if ((lane & 3) == 0)
                        atomicAdd(&attbuf[crow + f * 16 + r8 * 8], p);
                }
            if ((nt & 3) == 3) {
                __syncthreads();
                if (tid < 128) {
                    float v = 0.08838834764831845f * attbuf[tid];
                    g_att[(size_t)(e0 + tid) * H + h] = v;
                    atomicMax(&g_m[rs[tid] * H + h], encodeF(v));
                }
            }
        } else {
            // ---- p-half store ----
            const int colb = (nt - 16) * 32 + ccol;
#pragma unroll
            for (int f = 0; f < 2; f++) {
                int r0 = crow + f * 16;
#pragma unroll
                for (int j = 0; j < 2; j++) {
                    *(float2*)&g_Y[(size_t)(e0 + r0) * PHALF + colb + j * 8] =
                        make_float2(acc[f][j][0], acc[f][j][1]);
                    *(float2*)&g_Y[(size_t)(e0 + r0 + 8) * PHALF + colb + j * 8] =
                        make_float2(acc[f][j][2], acc[f][j][3]);
                }
            }
        }
    }
}

// ---------------- K4: exp + segment sum ------------------------------------
__global__ void k_exp(const int* __restrict__ row) {
    int i = blockIdx.x * 256 + threadIdx.x;
    if (i >= E_EDGES * H) return;
    int e = i >> 2, h = i & 3;
    int rw = row[e];
    float m = decodeF(g_m[rw * H + h]);
    float ev = __expf(g_att[i] - m);
    g_att[i] = ev;
    atomicAdd(&g_s[rw * H + h], ev);
}

// ---------------- K5: final, 64-edge tiles, 128 thr, 2 CTAs/SM -------------
#define SMF_WS  0                 // 256 floats
#define SMF_B1  1024
#define SMF_B2  1536
#define SMF_H1  2048              // 64 rows * 512B = 32KB
#define SMF_W2  (2048 + 32768)    // 128 rows * 512B = 64KB
#define SMEMF_SZ (2048 + 32768 + 65536)   // 98KB

__global__ void __launch_bounds__(128, 2) k_final(const int* __restrict__ row,
                                                  const float* __restrict__ b1,
                                                  const float* __restrict__ b2,
                                                  float* __restrict__ out) {
    extern __shared__ char smem[];
    float* ws  = (float*)(smem + SMF_WS);
    float* b1s = (float*)(smem + SMF_B1);
    float* b2s = (float*)(smem + SMF_B2);
    const int tid = threadIdx.x;
    const int lane = tid & 31, wid = tid >> 5;   // 4 warps
    const int e0 = blockIdx.x * 64;
    const uint32_t h1base = smem_u32(smem + SMF_H1);
    const uint32_t w2base = smem_u32(smem + SMF_W2);

    // prefetch full W2 tile (128 rows)
#pragma unroll
    for (int it = 0; it < 32; it++) {
        int i = it * 128 + tid;
        int r = i >> 5, c = i & 31;
        CP_ASYNC16(w2base + r * 512 + (((uint32_t)c ^ (r & 7)) << 4),
                   &g_W2r[(size_t)r * D + c * 4]);
    }
    CP_COMMIT();

    if (tid < 128) { b1s[tid] = b1[tid]; b2s[tid] = b2[tid]; }
#pragma unroll
    for (int it = 0; it < 2; it++) {
        int idx = it * 128 + tid;
        int e = e0 + (idx >> 2), h = idx & 3;
        ws[idx] = g_att[(size_t)e * H + h] / g_s[row[e] * H + h];
    }
    __syncthreads();

    // h1 = SiLU(sum_h w*p + b1), tf32-rounded into swizzled smem
#pragma unroll
    for (int it = 0; it < 64; it++) {
        int idx = it * 128 + tid;
        int m = idx >> 7, c = idx & 127;
        const float* yp = g_Y + (size_t)(e0 + m) * PHALF + c;
        const float4 w4 = *(const float4*)&ws[m * 4];
        float pre = b1s[c] + w4.x * yp[0] + w4.y * yp[128] + w4.z * yp[256] + w4.w * yp[384];
        float h1 = pre / (1.f + __expf(-pre));
        *(uint32_t*)(smem + SMF_H1 + m * 512 + ((((uint32_t)(c >> 2)) ^ (m & 7)) << 4)
                     + (c & 3) * 4) = tf32r(h1);
    }
    CP_WAIT0();
    __syncthreads();

    // mma: out = h1(64x128) @ W2^T(128x128); warp covers all M=64, n32 slice
    const int n_base = wid * 32;
    const int g8 = lane >> 3, l8 = lane & 7;
    uint32_t arow[4], asw[4];
#pragma unroll
    for (int f = 0; f < 4; f++) {
        int r = f * 16 + (g8 & 1) * 8 + l8;
        arow[f] = (uint32_t)r * 512;
        asw[f] = (uint32_t)(r & 7);
    }
    const uint32_t ack = (uint32_t)(g8 >> 1);
    uint32_t brow[2], bsw[2];
#pragma unroll
    for (int q = 0; q < 2; q++) {
        int r = n_base + q * 16 + (g8 >> 1) * 8 + l8;
        brow[q] = (uint32_t)r * 512;
        bsw[q] = (uint32_t)(r & 7);
    }
    const uint32_t bck = (uint32_t)(g8 & 1);

    float acc[4][4][4];
#pragma unroll
    for (int f = 0; f < 4; f++)
#pragma unroll
        for (int j = 0; j < 4; j++)
#pragma unroll
            for (int r = 0; r < 4; r++) acc[f][j][r] = 0.f;

#pragma unroll
    for (int ks = 0; ks < 16; ks++) {
        const uint32_t kk = (uint32_t)(ks * 2);
        uint32_t afr[4][4];
#pragma unroll
        for (int f = 0; f < 4; f++)
            ldsm4(afr[f], h1base + arow[f] + (((kk + ack) ^ asw[f]) << 4));
        uint32_t bfr[4][2];
#pragma unroll
        for (int q = 0; q < 2; q++) {
            uint32_t t4[4];
            ldsm4(t4, w2base + brow[q] + (((kk + bck) ^ bsw[q]) << 4));
            bfr[2 * q][0] = t4[0]; bfr[2 * q][1] = t4[1];
            bfr[2 * q + 1][0] = t4[2]; bfr[2 * q + 1][1] = t4[3];
        }
#pragma unroll
        for (int f = 0; f < 4; f++)
#pragma unroll
            for (int j = 0; j < 4; j++)
                mma_tf32(acc[f][j], afr[f], bfr[j]);
    }

    const int ccol = n_base + (lane & 3) * 2;
#pragma unroll
    for (int f = 0; f < 4; f++) {
        int r0 = e0 + f * 16 + (lane >> 2);
#pragma unroll
        for (int j = 0; j < 4; j++) {
            int col = ccol + j * 8;
            float bx = b2s[col], by = b2s[col + 1];
            *(float2*)&out[(size_t)r0 * D + col] =
                make_float2(acc[f][j][0] + bx, acc[f][j][1] + by);
            *(float2*)&out[(size_t)(r0 + 8) * D + col] =
                make_float2(acc[f][j][2] + bx, acc[f][j][3] + by);
        }
    }
}

// ---------------- launch ----------------------------------------------------
extern "C" void kernel_launch(void* const* d_in, const int* in_sizes, int n_in,
                              void* d_out, int out_size) {
    const float* Z     = (const float*)d_in[0];
    const int*   edges = (const int*)  d_in[1];
    const float* Wq    = (const float*)d_in[2];
    const float* Wk    = (const float*)d_in[3];
    const float* Wv    = (const float*)d_in[4];
    const float* W1    = (const float*)d_in[5];
    const float* b1    = (const float*)d_in[6];
    const float* W2    = (const float*)d_in[7];
    const float* b2    = (const float*)d_in[8];
    float* out = (float*)d_out;
    const int* row = edges;

    cudaFuncSetAttribute(k_mma, cudaFuncAttributeMaxDynamicSharedMemorySize, SMEM_SZ);
    cudaFuncSetAttribute(k_final, cudaFuncAttributeMaxDynamicSharedMemorySize, SMEMF_SZ);

    k_build<<<NCOMB + D, D>>>(Wq, Wk, Wv, W1, W2);
    k_init<<<(N_NODES * H + 255) / 256, 256>>>();
    k_nop<<<1, 1>>>();   // aligns ncu capture onto k_mma
    k_mma<<<E_EDGES / 128, 256, SMEM_SZ>>>(Z, row);
    k_exp<<<(E_EDGES * H + 255) / 256, 256>>>(row);
    k_final<<<E_EDGES / 64, 128, SMEMF_SZ>>>(row, b1, b2, out);
}

// round 10
// speedup vs baseline: 2.2376x; 1.8264x over previous
#include <cuda_runtime.h>
#include <cuda_fp16.h>
#include <cstdint>
#include <math.h>

#define E_EDGES 640000
#define N_NODES 10000
#define D 128
#define H 4
#define NCOMB 1024
#define PHALF 512

// ---------------- scratch ---------------------------------------------------
__device__ __align__(16) __half g_WcombH[NCOMB * D];             // fp16 combined weights
__device__ __align__(16) __half g_W2H[D * D];                    // fp16 W2 (row-major [j][i])
__device__ __align__(16) __half g_Yh[(size_t)E_EDGES * PHALF];   // p-half, fp16 (0.65 GB)
__device__ float    g_att[E_EDGES * H];
__device__ unsigned g_m[N_NODES * H];
__device__ float    g_s[N_NODES * H];

// ---------------- helpers ---------------------------------------------------
__device__ __forceinline__ uint32_t smem_u32(const void* p) {
    uint32_t a;
    asm("{ .reg .u64 t; cvta.to.shared.u64 t, %1; cvt.u32.u64 %0, t; }" : "=r"(a) : "l"(p));
    return a;
}
__device__ __forceinline__ void ldsm4(uint32_t* r, uint32_t addr) {
    asm volatile("ldmatrix.sync.aligned.m8n8.x4.shared.b16 {%0,%1,%2,%3}, [%4];"
                 : "=r"(r[0]), "=r"(r[1]), "=r"(r[2]), "=r"(r[3]) : "r"(addr));
}
__device__ __forceinline__ void mma_f16(float* d, const uint32_t* a, const uint32_t* b) {
    asm volatile("mma.sync.aligned.m16n8k16.row.col.f32.f16.f16.f32 "
                 "{%0,%1,%2,%3}, {%4,%5,%6,%7}, {%8,%9}, {%0,%1,%2,%3};"
                 : "+f"(d[0]), "+f"(d[1]), "+f"(d[2]), "+f"(d[3])
                 : "r"(a[0]), "r"(a[1]), "r"(a[2]), "r"(a[3]), "r"(b[0]), "r"(b[1]));
}
#define CP_ASYNC16(dst, src) \
    asm volatile("cp.async.cg.shared.global [%0], [%1], 16;" :: "r"(dst), "l"(src))
#define CP_COMMIT() asm volatile("cp.async.commit_group;" ::: "memory")
#define CP_WAIT0()  asm volatile("cp.async.wait_group 0;" ::: "memory")

__device__ __forceinline__ unsigned encodeF(float x) {
    unsigned u = __float_as_uint(x);
    return (u & 0x80000000u) ? ~u : (u | 0x80000000u);
}
__device__ __forceinline__ float decodeF(unsigned e) {
    unsigned u = (e & 0x80000000u) ? (e ^ 0x80000000u) : ~e;
    return __uint_as_float(u);
}

// fp16 smem tile addressing: row stride 256B (128 halfs), 16B chunks swizzled:
//   addr(row, c /*half idx*/) = base + row*256 + (((c>>3) ^ ((row&7)<<1))<<4) + (c&7)*2
__device__ __forceinline__ uint32_t htile_off(int row, int c) {
    return (uint32_t)(row * 256 + ((((c >> 3)) ^ ((row & 7) << 1)) << 4) + (c & 7) * 2);
}

// ---------------- K0: build combined weights (fp16) ------------------------
__global__ void k_build(const float* __restrict__ Wq, const float* __restrict__ Wk,
                        const float* __restrict__ Wv, const float* __restrict__ W1,
                        const float* __restrict__ W2) {
    int n = blockIdx.x;
    int f = threadIdx.x;
    if (n < NCOMB) {
        float acc = 0.f;
        if (n < H * D) {
            int h = n >> 7, g = n & 127;
            const float* wq = Wq + h * D * D;
            const float* wk = Wk + h * D * D;
            for (int d = 0; d < D; d++) acc += wq[d * D + f] * wk[d * D + g];
        } else {
            int m2 = n - H * D;
            int h = m2 >> 7, i = m2 & 127;
            const float* wv = Wv + h * D * D;
            for (int d = 0; d < D; d++) acc += W1[i * D + d] * wv[d * D + f];
        }
        g_WcombH[n * D + f] = __float2half_rn(acc);
    } else {
        int i = n - NCOMB;
        g_W2H[i * D + f] = __float2half_rn(W2[i * D + f]);
    }
}

// ---------------- K1: reset segment buffers --------------------------------
__global__ void k_init() {
    int i = blockIdx.x * 256 + threadIdx.x;
    if (i < N_NODES * H) { g_m[i] = 0u; g_s[i] = 0.f; }
}

// ---------------- dummy (profiler alignment) --------------------------------
__global__ void k_nop() {}

// ---------------- K2: fp16 mma GEMM (M=128, Nt=128, 8 warps 4Mx2N) ----------
#define SM_ATT 0                    // 128 floats
#define SM_ROW 512                  // 128 ints
#define SM_Z   1024                 // 128 rows * 256B = 32KB
#define SM_W0  (1024 + 32768)       // 128 rows * 256B = 32KB
#define SM_W1  (1024 + 65536)
#define SMEM_SZ (1024 + 98304)      // 99328 B (~97KB) -> 2 CTAs/SM

__global__ void __launch_bounds__(256, 2) k_mma(const float* __restrict__ Z,
                                                const int* __restrict__ row) {
    extern __shared__ char smem[];
    float* attbuf = (float*)(smem + SM_ATT);
    int* rs = (int*)(smem + SM_ROW);
    const int tid = threadIdx.x;
    const int lane = tid & 31, wid = tid >> 5;
    const int warpM = wid & 3, warpN = wid >> 2;      // 4M x 2N
    const int m_base = warpM * 32, n_base = warpN * 64;
    const int e0 = blockIdx.x * 128;

    const uint32_t zbase = smem_u32(smem + SM_Z);
    const uint32_t wbase[2] = { smem_u32(smem + SM_W0), smem_u32(smem + SM_W1) };

    if (tid < 128) rs[tid] = row[e0 + tid];

    // ---- Z tile: 128x128 -> fp16, swizzled ----
#pragma unroll
    for (int it = 0; it < 16; it++) {
        int i = it * 256 + tid;
        int r = i >> 5, c4 = (i & 31) * 4;
        float4 v = *(const float4*)&Z[(size_t)(e0 + r) * D + c4];
        __half2 lo = __floats2half2_rn(v.x, v.y);
        __half2 hi = __floats2half2_rn(v.z, v.w);
        uint2 w = { *(uint32_t*)&lo, *(uint32_t*)&hi };
        *(uint2*)(smem + SM_Z + htile_off(r, c4)) = w;
    }

    // ---- prefetch W n-tile 0 (128 rows, fp16) ----
#pragma unroll
    for (int it = 0; it < 8; it++) {
        int i = it * 256 + tid;
        int r = i >> 4, ch = i & 15;
        CP_ASYNC16(wbase[0] + r * 256 + (uint32_t)(((ch ^ ((r & 7) << 1))) << 4),
                   &g_WcombH[(size_t)r * D + ch * 8]);
    }
    CP_COMMIT();

    // ldmatrix lane addressing
    const int l16 = lane & 15;
    const int khi = lane >> 4;            // +0 / +1 k-chunk
    uint32_t arow[2], aswz[2];
#pragma unroll
    for (int f = 0; f < 2; f++) {
        int r = m_base + f * 16 + l16;
        arow[f] = (uint32_t)r * 256;
        aswz[f] = (uint32_t)((r & 7) << 1);
    }
    uint32_t brow[4], bswz[4];
#pragma unroll
    for (int q = 0; q < 4; q++) {
        int r = n_base + q * 16 + l16;
        brow[q] = (uint32_t)r * 256;
        bswz[q] = (uint32_t)((r & 7) << 1);
    }

    const int crow = m_base + (lane >> 2);
    const int ccol = n_base + (lane & 3) * 2;

    for (int nt = 0; nt < 8; nt++) {
        const int buf = nt & 1;
        CP_WAIT0();
        __syncthreads();
        if (nt < 7) {
#pragma unroll
            for (int it = 0; it < 8; it++) {
                int i = it * 256 + tid;
                int r = i >> 4, ch = i & 15;
                CP_ASYNC16(wbase[buf ^ 1] + r * 256 + (uint32_t)(((ch ^ ((r & 7) << 1))) << 4),
                           &g_WcombH[(size_t)(nt + 1) * 128 * D + (size_t)r * D + ch * 8]);
            }
            CP_COMMIT();
        }

        float acc[2][8][4];
#pragma unroll
        for (int f = 0; f < 2; f++)
#pragma unroll
            for (int j = 0; j < 8; j++)
#pragma unroll
                for (int r = 0; r < 4; r++) acc[f][j][r] = 0.f;

        const uint32_t wb = wbase[buf];
#pragma unroll
        for (int ks = 0; ks < 8; ks++) {            // k16 per step
            const uint32_t kc = (uint32_t)(ks * 2 + khi);   // chunk idx
            uint32_t afr[2][4];
#pragma unroll
            for (int f = 0; f < 2; f++)
                ldsm4(afr[f], zbase + arow[f] + ((kc ^ aswz[f]) << 4));
            uint32_t bfr[8][2];
#pragma unroll
            for (int q = 0; q < 4; q++) {
                uint32_t t4[4];
                ldsm4(t4, wb + brow[q] + ((kc ^ bswz[q]) << 4));   // NON-trans: B rows are n, k contiguous
                bfr[2 * q][0] = t4[0]; bfr[2 * q][1] = t4[2];
                bfr[2 * q + 1][0] = t4[1]; bfr[2 * q + 1][1] = t4[3];
            }
#pragma unroll
            for (int f = 0; f < 2; f++)
#pragma unroll
                for (int j = 0; j < 8; j++)
                    mma_f16(acc[f][j], afr[f], bfr[j]);
        }

        if (nt < 4) {
            // ---- fused att epilogue + segment max (head = nt) ----
            if (tid < 128) attbuf[tid] = 0.f;
            __syncthreads();
            float part[2][2] = {{0.f, 0.f}, {0.f, 0.f}};
#pragma unroll
            for (int f = 0; f < 2; f++)
#pragma unroll
                for (int j = 0; j < 8; j++) {
                    int col = ccol + j * 8;
#pragma unroll
                    for (int r8 = 0; r8 < 2; r8++) {
                        int rr = crow + f * 16 + r8 * 8;
                        __half2 zh = *(const __half2*)(smem + SM_Z + htile_off(rr, col));
                        float2 z = __half22float2(zh);
                        part[f][r8] += acc[f][j][r8 * 2] * z.x + acc[f][j][r8 * 2 + 1] * z.y;
                    }
                }
#pragma unroll
            for (int f = 0; f < 2; f++)
#pragma unroll
                for (int r8 = 0; r8 < 2; r8++) {
                    float p = part[f][r8];
                    p += __shfl_xor_sync(0xFFFFFFFFu, p, 1);
                    p += __shfl_xor_sync(0xFFFFFFFFu, p, 2);
                    if ((lane & 3) == 0)
                        atomicAdd(&attbuf[crow + f * 16 + r8 * 8], p);
                }
            __syncthreads();
            if (tid < 128) {
                float v = 0.08838834764831845f * attbuf[tid];
                g_att[(size_t)(e0 + tid) * H + nt] = v;
                atomicMax(&g_m[rs[tid] * H + nt], encodeF(v));
            }
        } else {
            // ---- p-half store (fp16) ----
            const int colb = (nt - 4) * 128 + ccol;
#pragma unroll
            for (int f = 0; f < 2; f++) {
                int r0 = crow + f * 16;
#pragma unroll
                for (int j = 0; j < 8; j++) {
                    __half2 v0 = __floats2half2_rn(acc[f][j][0], acc[f][j][1]);
                    __half2 v1 = __floats2half2_rn(acc[f][j][2], acc[f][j][3]);
                    *(__half2*)&g_Yh[(size_t)(e0 + r0) * PHALF + colb + j * 8] = v0;
                    *(__half2*)&g_Yh[(size_t)(e0 + r0 + 8) * PHALF + colb + j * 8] = v1;
                }
            }
        }
    }
}

// ---------------- K4: exp + segment sum ------------------------------------
__global__ void k_exp(const int* __restrict__ row) {
    int i = blockIdx.x * 256 + threadIdx.x;
    if (i >= E_EDGES * H) return;
    int e = i >> 2, h = i & 3;
    int rw = row[e];
    float m = decodeF(g_m[rw * H + h]);
    float ev = __expf(g_att[i] - m);
    g_att[i] = ev;
    atomicAdd(&g_s[rw * H + h], ev);
}

// ---------------- K5: final (fp16 operands): w -> h1(SiLU) -> @W2^T + b2 ---
#define SMF_WS  0                 // 256 floats
#define SMF_B1  1024
#define SMF_B2  1536
#define SMF_H1  2048              // 64 rows * 256B = 16KB
#define SMF_W2  (2048 + 16384)    // 128 rows * 256B = 32KB
#define SMEMF_SZ (2048 + 16384 + 32768)   // ~50KB -> 2 CTAs/SM

__global__ void __launch_bounds__(128, 2) k_final(const int* __restrict__ row,
                                                  const float* __restrict__ b1,
                                                  const float* __restrict__ b2,
                                                  float* __restrict__ out) {
    extern __shared__ char smem[];
    float* ws  = (float*)(smem + SMF_WS);
    float* b1s = (float*)(smem + SMF_B1);
    float* b2s = (float*)(smem + SMF_B2);
    const int tid = threadIdx.x;
    const int lane = tid & 31, wid = tid >> 5;   // 4 warps
    const int e0 = blockIdx.x * 64;
    const uint32_t h1base = smem_u32(smem + SMF_H1);
    const uint32_t w2base = smem_u32(smem + SMF_W2);

    // prefetch W2 tile (fp16, 128 rows)
#pragma unroll
    for (int it = 0; it < 16; it++) {
        int i = it * 128 + tid;
        int r = i >> 4, ch = i & 15;
        CP_ASYNC16(w2base + r * 256 + (uint32_t)(((ch ^ ((r & 7) << 1))) << 4),
                   &g_W2H[(size_t)r * D + ch * 8]);
    }
    CP_COMMIT();

    if (tid < 128) { b1s[tid] = b1[tid]; b2s[tid] = b2[tid]; }
#pragma unroll
    for (int it = 0; it < 2; it++) {
        int idx = it * 128 + tid;
        int e = e0 + (idx >> 2), h = idx & 3;
        ws[idx] = g_att[(size_t)e * H + h] / g_s[row[e] * H + h];
    }
    __syncthreads();

    // h1 = SiLU(sum_h w*p + b1) -> fp16 swizzled smem
#pragma unroll
    for (int it = 0; it < 64; it++) {
        int idx = it * 128 + tid;
        int m = idx >> 7, c = idx & 127;
        const __half* yp = g_Yh + (size_t)(e0 + m) * PHALF + c;
        const float4 w4 = *(const float4*)&ws[m * 4];
        float pre = b1s[c] + w4.x * __half2float(yp[0])   + w4.y * __half2float(yp[128])
                           + w4.z * __half2float(yp[256]) + w4.w * __half2float(yp[384]);
        float h1 = pre / (1.f + __expf(-pre));
        *(__half*)(smem + SMF_H1 + htile_off(m, c)) = __float2half_rn(h1);
    }
    CP_WAIT0();
    __syncthreads();

    // mma: out = h1(64x128) @ W2^T; warp covers all M=64, n32 slice
    const int n_base = wid * 32;
    const int l16 = lane & 15;
    const int khi = lane >> 4;
    uint32_t arow[4], aswz[4];
#pragma unroll
    for (int f = 0; f < 4; f++) {
        int r = f * 16 + l16;
        arow[f] = (uint32_t)r * 256;
        aswz[f] = (uint32_t)((r & 7) << 1);
    }
    uint32_t brow[2], bswz[2];
#pragma unroll
    for (int q = 0; q < 2; q++) {
        int r = n_base + q * 16 + l16;
        brow[q] = (uint32_t)r * 256;
        bswz[q] = (uint32_t)((r & 7) << 1);
    }

    float acc[4][4][4];
#pragma unroll
    for (int f = 0; f < 4; f++)
#pragma unroll
        for (int j = 0; j < 4; j++)
#pragma unroll
            for (int r = 0; r < 4; r++) acc[f][j][r] = 0.f;

#pragma unroll
    for (int ks = 0; ks < 8; ks++) {
        const uint32_t kc = (uint32_t)(ks * 2 + khi);
        uint32_t afr[4][4];
#pragma unroll
        for (int f = 0; f < 4; f++)
            ldsm4(afr[f], h1base + arow[f] + ((kc ^ aswz[f]) << 4));
        uint32_t bfr[4][2];
#pragma unroll
        for (int q = 0; q < 2; q++) {
            uint32_t t4[4];
            ldsm4(t4, w2base + brow[q] + ((kc ^ bswz[q]) << 4));   // NON-trans
            bfr[2 * q][0] = t4[0]; bfr[2 * q][1] = t4[2];
            bfr[2 * q + 1][0] = t4[1]; bfr[2 * q + 1][1] = t4[3];
        }
#pragma unroll
        for (int f = 0; f < 4; f++)
#pragma unroll
            for (int j = 0; j < 4; j++)
                mma_f16(acc[f][j], afr[f], bfr[j]);
    }

    const int ccol = n_base + (lane & 3) * 2;
#pragma unroll
    for (int f = 0; f < 4; f++) {
        int r0 = e0 + f * 16 + (lane >> 2);
#pragma unroll
        for (int j = 0; j < 4; j++) {
            int col = ccol + j * 8;
            float bx = b2s[col], by = b2s[col + 1];
            *(float2*)&out[(size_t)r0 * D + col] =
                make_float2(acc[f][j][0] + bx, acc[f][j][1] + by);
            *(float2*)&out[(size_t)(r0 + 8) * D + col] =
                make_float2(acc[f][j][2] + bx, acc[f][j][3] + by);
        }
    }
}

// ---------------- launch ----------------------------------------------------
extern "C" void kernel_launch(void* const* d_in, const int* in_sizes, int n_in,
                              void* d_out, int out_size) {
    const float* Z     = (const float*)d_in[0];
    const int*   edges = (const int*)  d_in[1];
    const float* Wq    = (const float*)d_in[2];
    const float* Wk    = (const float*)d_in[3];
    const float* Wv    = (const float*)d_in[4];
    const float* W1    = (const float*)d_in[5];
    const float* b1    = (const float*)d_in[6];
    const float* W2    = (const float*)d_in[7];
    const float* b2    = (const float*)d_in[8];
    float* out = (float*)d_out;
    const int* row = edges;

    cudaFuncSetAttribute(k_mma, cudaFuncAttributeMaxDynamicSharedMemorySize, SMEM_SZ);
    cudaFuncSetAttribute(k_final, cudaFuncAttributeMaxDynamicSharedMemorySize, SMEMF_SZ);

    k_build<<<NCOMB + D, D>>>(Wq, Wk, Wv, W1, W2);
    k_init<<<(N_NODES * H + 255) / 256, 256>>>();
    k_nop<<<1, 1>>>();   // aligns ncu capture onto k_mma
    k_mma<<<E_EDGES / 128, 256, SMEM_SZ>>>(Z, row);
    k_exp<<<(E_EDGES * H + 255) / 256, 256>>>(row);
    k_final<<<E_EDGES / 64, 128, SMEMF_SZ>>>(row, b1, b2, out);
}

// round 12
// speedup vs baseline: 2.4496x; 1.0947x over previous
#include <cuda_runtime.h>
#include <cuda_fp16.h>
#include <cstdint>
#include <math.h>

#define E_EDGES 640000
#define N_NODES 10000
#define D 128
#define H 4
#define NCOMB 1024
#define PHALF 512

// ---------------- scratch ---------------------------------------------------
__device__ __align__(16) __half g_WcombH[NCOMB * D];             // fp16 combined weights
__device__ __align__(16) __half g_W2H[D * D];                    // fp16 W2 (row-major [j][i])
__device__ __align__(16) __half g_Yh[(size_t)E_EDGES * PHALF];   // p-half, fp16 (0.65 GB)
__device__ float    g_att[E_EDGES * H];
__device__ unsigned g_m[N_NODES * H];
__device__ float    g_s[N_NODES * H];

// ---------------- helpers ---------------------------------------------------
__device__ __forceinline__ uint32_t smem_u32(const void* p) {
    uint32_t a;
    asm("{ .reg .u64 t; cvta.to.shared.u64 t, %1; cvt.u32.u64 %0, t; }" : "=r"(a) : "l"(p));
    return a;
}
__device__ __forceinline__ void ldsm4(uint32_t* r, uint32_t addr) {
    asm volatile("ldmatrix.sync.aligned.m8n8.x4.shared.b16 {%0,%1,%2,%3}, [%4];"
                 : "=r"(r[0]), "=r"(r[1]), "=r"(r[2]), "=r"(r[3]) : "r"(addr));
}
__device__ __forceinline__ void mma_f16(float* d, const uint32_t* a, const uint32_t* b) {
    asm volatile("mma.sync.aligned.m16n8k16.row.col.f32.f16.f16.f32 "
                 "{%0,%1,%2,%3}, {%4,%5,%6,%7}, {%8,%9}, {%0,%1,%2,%3};"
                 : "+f"(d[0]), "+f"(d[1]), "+f"(d[2]), "+f"(d[3])
                 : "r"(a[0]), "r"(a[1]), "r"(a[2]), "r"(a[3]), "r"(b[0]), "r"(b[1]));
}
#define CP_ASYNC16(dst, src) \
    asm volatile("cp.async.cg.shared.global [%0], [%1], 16;" :: "r"(dst), "l"(src))
#define CP_COMMIT() asm volatile("cp.async.commit_group;" ::: "memory")
#define CP_WAIT0()  asm volatile("cp.async.wait_group 0;" ::: "memory")

__device__ __forceinline__ unsigned encodeF(float x) {
    unsigned u = __float_as_uint(x);
    return (u & 0x80000000u) ? ~u : (u | 0x80000000u);
}
__device__ __forceinline__ float decodeF(unsigned e) {
    unsigned u = (e & 0x80000000u) ? (e ^ 0x80000000u) : ~e;
    return __uint_as_float(u);
}

// fp16 smem tile addressing: row stride 256B (128 halfs), 16B chunks swizzled.
// CONFLICT-FREE: chunk ^= row&7 permutes chunk bits 0..2, so the 8 rows of an
// ldmatrix footprint hit 8 distinct bank groups.
//   addr(row, c /*half idx*/) = base + row*256 + (((c>>3) ^ (row&7))<<4) + (c&7)*2
__device__ __forceinline__ uint32_t htile_off(int row, int c) {
    return (uint32_t)(row * 256 + ((((c >> 3)) ^ (row & 7)) << 4) + (c & 7) * 2);
}

// ---------------- K0: build combined weights (fp16) ------------------------
__global__ void k_build(const float* __restrict__ Wq, const float* __restrict__ Wk,
                        const float* __restrict__ Wv, const float* __restrict__ W1,
                        const float* __restrict__ W2) {
    int n = blockIdx.x;
    int f = threadIdx.x;
    if (n < NCOMB) {
        float acc = 0.f;
        if (n < H * D) {
            int h = n >> 7, g = n & 127;
            const float* wq = Wq + h * D * D;
            const float* wk = Wk + h * D * D;
            for (int d = 0; d < D; d++) acc += wq[d * D + f] * wk[d * D + g];
        } else {
            int m2 = n - H * D;
            int h = m2 >> 7, i = m2 & 127;
            const float* wv = Wv + h * D * D;
            for (int d = 0; d < D; d++) acc += W1[i * D + d] * wv[d * D + f];
        }
        g_WcombH[n * D + f] = __float2half_rn(acc);
    } else {
        int i = n - NCOMB;
        g_W2H[i * D + f] = __float2half_rn(W2[i * D + f]);
    }
}

// ---------------- K1: reset segment buffers --------------------------------
__global__ void k_init() {
    int i = blockIdx.x * 256 + threadIdx.x;
    if (i < N_NODES * H) { g_m[i] = 0u; g_s[i] = 0.f; }
}

// ---------------- dummy (profiler alignment) --------------------------------
__global__ void k_nop() {}

// ---------------- K2: fp16 mma GEMM (M=128, Nt=128, 8 warps 4Mx2N) ----------
#define SM_ATT 0                    // 128 floats
#define SM_ROW 512                  // 128 ints
#define SM_Z   1024                 // 128 rows * 256B = 32KB
#define SM_W0  (1024 + 32768)       // 128 rows * 256B = 32KB
#define SM_W1  (1024 + 65536)
#define SMEM_SZ (1024 + 98304)      // 99328 B (~97KB) -> 2 CTAs/SM

__global__ void __launch_bounds__(256, 2) k_mma(const float* __restrict__ Z,
                                                const int* __restrict__ row) {
    extern __shared__ char smem[];
    float* attbuf = (float*)(smem + SM_ATT);
    int* rs = (int*)(smem + SM_ROW);
    const int tid = threadIdx.x;
    const int lane = tid & 31, wid = tid >> 5;
    const int warpM = wid & 3, warpN = wid >> 2;      // 4M x 2N
    const int m_base = warpM * 32, n_base = warpN * 64;
    const int e0 = blockIdx.x * 128;

    const uint32_t zbase = smem_u32(smem + SM_Z);
    const uint32_t wbase[2] = { smem_u32(smem + SM_W0), smem_u32(smem + SM_W1) };

    if (tid < 128) rs[tid] = row[e0 + tid];

    // ---- Z tile: 128x128 -> fp16, swizzled ----
#pragma unroll
    for (int it = 0; it < 16; it++) {
        int i = it * 256 + tid;
        int r = i >> 5, c4 = (i & 31) * 4;
        float4 v = *(const float4*)&Z[(size_t)(e0 + r) * D + c4];
        __half2 lo = __floats2half2_rn(v.x, v.y);
        __half2 hi = __floats2half2_rn(v.z, v.w);
        uint2 w = { *(uint32_t*)&lo, *(uint32_t*)&hi };
        *(uint2*)(smem + SM_Z + htile_off(r, c4)) = w;
    }

    // ---- prefetch W n-tile 0 (128 rows, fp16) ----
#pragma unroll
    for (int it = 0; it < 8; it++) {
        int i = it * 256 + tid;
        int r = i >> 4, ch = i & 15;
        CP_ASYNC16(wbase[0] + r * 256 + (uint32_t)((ch ^ (r & 7)) << 4),
                   &g_WcombH[(size_t)r * D + ch * 8]);
    }
    CP_COMMIT();

    // ldmatrix lane addressing
    const int l16 = lane & 15;
    const int khi = lane >> 4;            // +0 / +1 k-chunk
    uint32_t arow[2], aswz[2];
#pragma unroll
    for (int f = 0; f < 2; f++) {
        int r = m_base + f * 16 + l16;
        arow[f] = (uint32_t)r * 256;
        aswz[f] = (uint32_t)(r & 7);
    }
    uint32_t brow[4], bswz[4];
#pragma unroll
    for (int q = 0; q < 4; q++) {
        int r = n_base + q * 16 + l16;
        brow[q] = (uint32_t)r * 256;
        bswz[q] = (uint32_t)(r & 7);
    }

    const int crow = m_base + (lane >> 2);
    const int ccol = n_base + (lane & 3) * 2;

    for (int nt = 0; nt < 8; nt++) {
        const int buf = nt & 1;
        CP_WAIT0();
        __syncthreads();
        if (nt < 7) {
#pragma unroll
            for (int it = 0; it < 8; it++) {
                int i = it * 256 + tid;
                int r = i >> 4, ch = i & 15;
                CP_ASYNC16(wbase[buf ^ 1] + r * 256 + (uint32_t)((ch ^ (r & 7)) << 4),
                           &g_WcombH[(size_t)(nt + 1) * 128 * D + (size_t)r * D + ch * 8]);
            }
            CP_COMMIT();
        }

        float acc[2][8][4];
#pragma unroll
        for (int f = 0; f < 2; f++)
#pragma unroll
            for (int j = 0; j < 8; j++)
#pragma unroll
                for (int r = 0; r < 4; r++) acc[f][j][r] = 0.f;

        const uint32_t wb = wbase[buf];
#pragma unroll
        for (int ks = 0; ks < 8; ks++) {            // k16 per step
            const uint32_t kc = (uint32_t)(ks * 2 + khi);   // chunk idx
            uint32_t afr[2][4];
#pragma unroll
            for (int f = 0; f < 2; f++)
                ldsm4(afr[f], zbase + arow[f] + ((kc ^ aswz[f]) << 4));
            uint32_t bfr[8][2];
#pragma unroll
            for (int q = 0; q < 4; q++) {
                uint32_t t4[4];
                ldsm4(t4, wb + brow[q] + ((kc ^ bswz[q]) << 4));   // non-trans: B rows are n, k contiguous
                bfr[2 * q][0] = t4[0]; bfr[2 * q][1] = t4[2];
                bfr[2 * q + 1][0] = t4[1]; bfr[2 * q + 1][1] = t4[3];
            }
#pragma unroll
            for (int f = 0; f < 2; f++)
#pragma unroll
                for (int j = 0; j < 8; j++)
                    mma_f16(acc[f][j], afr[f], bfr[j]);
        }

        if (nt < 4) {
            // ---- fused att epilogue + segment max (head = nt) ----
            if (tid < 128) attbuf[tid] = 0.f;
            __syncthreads();
            float part[2][2] = {{0.f, 0.f}, {0.f, 0.f}};
#pragma unroll
            for (int f = 0; f < 2; f++)
#pragma unroll
                for (int j = 0; j < 8; j++) {
                    int col = ccol + j * 8;
#pragma unroll
                    for (int r8 = 0; r8 < 2; r8++) {
                        int rr = crow + f * 16 + r8 * 8;
                        __half2 zh = *(const __half2*)(smem + SM_Z + htile_off(rr, col));
                        float2 z = __half22float2(zh);
                        part[f][r8] += acc[f][j][r8 * 2] * z.x + acc[f][j][r8 * 2 + 1] * z.y;
                    }
                }
#pragma unroll
            for (int f = 0; f < 2; f++)
#pragma unroll
                for (int r8 = 0; r8 < 2; r8++) {
                    float p = part[f][r8];
                    p += __shfl_xor_sync(0xFFFFFFFFu, p, 1);
                    p += __shfl_xor_sync(0xFFFFFFFFu, p, 2);
                    if ((lane & 3) == 0)
                        atomicAdd(&attbuf[crow + f * 16 + r8 * 8], p);
                }
            __syncthreads();
            if (tid < 128) {
                float v = 0.08838834764831845f * attbuf[tid];
                g_att[(size_t)(e0 + tid) * H + nt] = v;
                atomicMax(&g_m[rs[tid] * H + nt], encodeF(v));
            }
        } else {
            // ---- p-half store (fp16) ----
            const int colb = (nt - 4) * 128 + ccol;
#pragma unroll
            for (int f = 0; f < 2; f++) {
                int r0 = crow + f * 16;
#pragma unroll
                for (int j = 0; j < 8; j++) {
                    __half2 v0 = __floats2half2_rn(acc[f][j][0], acc[f][j][1]);
                    __half2 v1 = __floats2half2_rn(acc[f][j][2], acc[f][j][3]);
                    *(__half2*)&g_Yh[(size_t)(e0 + r0) * PHALF + colb + j * 8] = v0;
                    *(__half2*)&g_Yh[(size_t)(e0 + r0 + 8) * PHALF + colb + j * 8] = v1;
                }
            }
        }
    }
}

// ---------------- K4: exp + segment sum ------------------------------------
__global__ void k_exp(const int* __restrict__ row) {
    int i = blockIdx.x * 256 + threadIdx.x;
    if (i >= E_EDGES * H) return;
    int e = i >> 2, h = i & 3;
    int rw = row[e];
    float m = decodeF(g_m[rw * H + h]);
    float ev = __expf(g_att[i] - m);
    g_att[i] = ev;
    atomicAdd(&g_s[rw * H + h], ev);
}

// ---------------- K5: final (fp16 operands): w -> h1(SiLU) -> @W2^T + b2 ---
#define SMF_WS  0                 // 256 floats
#define SMF_B1  1024
#define SMF_B2  1536
#define SMF_H1  2048              // 64 rows * 256B = 16KB
#define SMF_W2  (2048 + 16384)    // 128 rows * 256B = 32KB
#define SMEMF_SZ (2048 + 16384 + 32768)   // ~50KB -> 2 CTAs/SM

__global__ void __launch_bounds__(128, 2) k_final(const int* __restrict__ row,
                                                  const float* __restrict__ b1,
                                                  const float* __restrict__ b2,
                                                  float* __restrict__ out) {
    extern __shared__ char smem[];
    float* ws  = (float*)(smem + SMF_WS);
    float* b1s = (float*)(smem + SMF_B1);
    float* b2s = (float*)(smem + SMF_B2);
    const int tid = threadIdx.x;
    const int lane = tid & 31, wid = tid >> 5;   // 4 warps
    const int e0 = blockIdx.x * 64;
    const uint32_t h1base = smem_u32(smem + SMF_H1);
    const uint32_t w2base = smem_u32(smem + SMF_W2);

    // prefetch W2 tile (fp16, 128 rows)
#pragma unroll
    for (int it = 0; it < 16; it++) {
        int i = it * 128 + tid;
        int r = i >> 4, ch = i & 15;
        CP_ASYNC16(w2base + r * 256 + (uint32_t)((ch ^ (r & 7)) << 4),
                   &g_W2H[(size_t)r * D + ch * 8]);
    }
    CP_COMMIT();

    if (tid < 128) { b1s[tid] = b1[tid]; b2s[tid] = b2[tid]; }
#pragma unroll
    for (int it = 0; it < 2; it++) {
        int idx = it * 128 + tid;
        int e = e0 + (idx >> 2), h = idx & 3;
        ws[idx] = g_att[(size_t)e * H + h] / g_s[row[e] * H + h];
    }
    __syncthreads();

    // h1 = SiLU(sum_h w*p + b1) -> fp16 swizzled smem
#pragma unroll
    for (int it = 0; it < 64; it++) {
        int idx = it * 128 + tid;
        int m = idx >> 7, c = idx & 127;
        const __half* yp = g_Yh + (size_t)(e0 + m) * PHALF + c;
        const float4 w4 = *(const float4*)&ws[m * 4];
        float pre = b1s[c] + w4.x * __half2float(yp[0])   + w4.y * __half2float(yp[128])
                           + w4.z * __half2float(yp[256]) + w4.w * __half2float(yp[384]);
        float h1 = pre / (1.f + __expf(-pre));
        *(__half*)(smem + SMF_H1 + htile_off(m, c)) = __float2half_rn(h1);
    }
    CP_WAIT0();
    __syncthreads();

    // mma: out = h1(64x128) @ W2^T; warp covers all M=64, n32 slice
    const int n_base = wid * 32;
    const int l16 = lane & 15;
    const int khi = lane >> 4;
    uint32_t arow[4], aswz[4];
#pragma unroll
    for (int f = 0; f < 4; f++) {
        int r = f * 16 + l16;
        arow[f] = (uint32_t)r * 256;
        aswz[f] = (uint32_t)(r & 7);
    }
    uint32_t brow[2], bswz[2];
#pragma unroll
    for (int q = 0; q < 2; q++) {
        int r = n_base + q * 16 + l16;
        brow[q] = (uint32_t)r * 256;
        bswz[q] = (uint32_t)(r & 7);
    }

    float acc[4][4][4];
#pragma unroll
    for (int f = 0; f < 4; f++)
#pragma unroll
        for (int j = 0; j < 4; j++)
#pragma unroll
            for (int r = 0; r < 4; r++) acc[f][j][r] = 0.f;

#pragma unroll
    for (int ks = 0; ks < 8; ks++) {
        const uint32_t kc = (uint32_t)(ks * 2 + khi);
        uint32_t afr[4][4];
#pragma unroll
        for (int f = 0; f < 4; f++)
            ldsm4(afr[f], h1base + arow[f] + ((kc ^ aswz[f]) << 4));
        uint32_t bfr[4][2];
#pragma unroll
        for (int q = 0; q < 2; q++) {
            uint32_t t4[4];
            ldsm4(t4, w2base + brow[q] + ((kc ^ bswz[q]) << 4));   // non-trans
            bfr[2 * q][0] = t4[0]; bfr[2 * q][1] = t4[2];
            bfr[2 * q + 1][0] = t4[1]; bfr[2 * q + 1][1] = t4[3];
        }
#pragma unroll
        for (int f = 0; f < 4; f++)
#pragma unroll
            for (int j = 0; j < 4; j++)
                mma_f16(acc[f][j], afr[f], bfr[j]);
    }

    const int ccol = n_base + (lane & 3) * 2;
#pragma unroll
    for (int f = 0; f < 4; f++) {
        int r0 = e0 + f * 16 + (lane >> 2);
#pragma unroll
        for (int j = 0; j < 4; j++) {
            int col = ccol + j * 8;
            float bx = b2s[col], by = b2s[col + 1];
            *(float2*)&out[(size_t)r0 * D + col] =
                make_float2(acc[f][j][0] + bx, acc[f][j][1] + by);
            *(float2*)&out[(size_t)(r0 + 8) * D + col] =
                make_float2(acc[f][j][2] + bx, acc[f][j][3] + by);
        }
    }
}

// ---------------- launch ----------------------------------------------------
extern "C" void kernel_launch(void* const* d_in, const int* in_sizes, int n_in,
                              void* d_out, int out_size) {
    const float* Z     = (const float*)d_in[0];
    const int*   edges = (const int*)  d_in[1];
    const float* Wq    = (const float*)d_in[2];
    const float* Wk    = (const float*)d_in[3];
    const float* Wv    = (const float*)d_in[4];
    const float* W1    = (const float*)d_in[5];
    const float* b1    = (const float*)d_in[6];
    const float* W2    = (const float*)d_in[7];
    const float* b2    = (const float*)d_in[8];
    float* out = (float*)d_out;
    const int* row = edges;

    cudaFuncSetAttribute(k_mma, cudaFuncAttributeMaxDynamicSharedMemorySize, SMEM_SZ);
    cudaFuncSetAttribute(k_final, cudaFuncAttributeMaxDynamicSharedMemorySize, SMEMF_SZ);

    k_build<<<NCOMB + D, D>>>(Wq, Wk, Wv, W1, W2);
    k_init<<<(N_NODES * H + 255) / 256, 256>>>();
    k_nop<<<1, 1>>>();   // aligns ncu capture onto k_mma
    k_mma<<<E_EDGES / 128, 256, SMEM_SZ>>>(Z, row);
    k_exp<<<(E_EDGES * H + 255) / 256, 256>>>(row);
    k_final<<<E_EDGES / 64, 128, SMEMF_SZ>>>(row, b1, b2, out);
}

// round 14
// speedup vs baseline: 3.5506x; 1.4495x over previous
#include <cuda_runtime.h>
#include <cuda_fp16.h>
#include <cstdint>
#include <math.h>

#define E_EDGES 640000
#define N_NODES 10000
#define D 128
#define H 4
#define NCOMB 1024
#define PHALF 512

// ---------------- scratch ---------------------------------------------------
__device__ __align__(16) __half g_WcombH[NCOMB * D];             // fp16 combined weights
__device__ __align__(16) __half g_W2H[D * D];                    // fp16 W2 (row-major [j][i])
__device__ __align__(16) __half g_Yh[(size_t)E_EDGES * PHALF];   // p-half, fp16 (0.65 GB)
__device__ float    g_att[E_EDGES * H];
__device__ unsigned g_m[N_NODES * H];
__device__ float    g_s[N_NODES * H];

// ---------------- helpers ---------------------------------------------------
__device__ __forceinline__ uint32_t smem_u32(const void* p) {
    uint32_t a;
    asm("{ .reg .u64 t; cvta.to.shared.u64 t, %1; cvt.u32.u64 %0, t; }" : "=r"(a) : "l"(p));
    return a;
}
__device__ __forceinline__ void ldsm4(uint32_t* r, uint32_t addr) {
    asm volatile("ldmatrix.sync.aligned.m8n8.x4.shared.b16 {%0,%1,%2,%3}, [%4];"
                 : "=r"(r[0]), "=r"(r[1]), "=r"(r[2]), "=r"(r[3]) : "r"(addr));
}
__device__ __forceinline__ void mma_f16(float* d, const uint32_t* a, const uint32_t* b) {
    asm volatile("mma.sync.aligned.m16n8k16.row.col.f32.f16.f16.f32 "
                 "{%0,%1,%2,%3}, {%4,%5,%6,%7}, {%8,%9}, {%0,%1,%2,%3};"
                 : "+f"(d[0]), "+f"(d[1]), "+f"(d[2]), "+f"(d[3])
                 : "r"(a[0]), "r"(a[1]), "r"(a[2]), "r"(a[3]), "r"(b[0]), "r"(b[1]));
}
#define CP_ASYNC16(dst, src) \
    asm volatile("cp.async.cg.shared.global [%0], [%1], 16;" :: "r"(dst), "l"(src))
#define CP_COMMIT() asm volatile("cp.async.commit_group;" ::: "memory")
#define CP_WAIT0()  asm volatile("cp.async.wait_group 0;" ::: "memory")

__device__ __forceinline__ unsigned encodeF(float x) {
    unsigned u = __float_as_uint(x);
    return (u & 0x80000000u) ? ~u : (u | 0x80000000u);
}
__device__ __forceinline__ float decodeF(unsigned e) {
    unsigned u = (e & 0x80000000u) ? (e ^ 0x80000000u) : ~e;
    return __uint_as_float(u);
}

// fp16 smem tile addressing: row stride 256B (128 halfs), 16B chunks swizzled.
// CONFLICT-FREE: chunk ^= row&7 (full 3-bit XOR).
__device__ __forceinline__ uint32_t htile_off(int row, int c) {
    return (uint32_t)(row * 256 + ((((c >> 3)) ^ (row & 7)) << 4) + (c & 7) * 2);
}

// ---------------- K0: build combined weights (fp16) ------------------------
__global__ void k_build(const float* __restrict__ Wq, const float* __restrict__ Wk,
                        const float* __restrict__ Wv, const float* __restrict__ W1,
                        const float* __restrict__ W2) {
    int n = blockIdx.x;
    int f = threadIdx.x;
    if (n < NCOMB) {
        float acc = 0.f;
        if (n < H * D) {
            int h = n >> 7, g = n & 127;
            const float* wq = Wq + h * D * D;
            const float* wk = Wk + h * D * D;
            for (int d = 0; d < D; d++) acc += wq[d * D + f] * wk[d * D + g];
        } else {
            int m2 = n - H * D;
            int h = m2 >> 7, i = m2 & 127;
            const float* wv = Wv + h * D * D;
            for (int d = 0; d < D; d++) acc += W1[i * D + d] * wv[d * D + f];
        }
        g_WcombH[n * D + f] = __float2half_rn(acc);
    } else {
        int i = n - NCOMB;
        g_W2H[i * D + f] = __float2half_rn(W2[i * D + f]);
    }
}

// ---------------- K1: reset segment buffers --------------------------------
__global__ void k_init() {
    int i = blockIdx.x * 256 + threadIdx.x;
    if (i < N_NODES * H) { g_m[i] = 0u; g_s[i] = 0.f; }
}

// ---------------- dummy (profiler alignment) --------------------------------
__global__ void k_nop() {}

// ---------------- K2: fp16 mma GEMM (M=128, Nt=128, 8 warps 4Mx2N) ----------
#define SM_ATT 0                    // 128 floats
#define SM_ROW 512                  // 128 ints
#define SM_Z   1024                 // 128 rows * 256B = 32KB
#define SM_W0  (1024 + 32768)       // 128 rows * 256B = 32KB
#define SM_W1  (1024 + 65536)
#define SMEM_SZ (1024 + 98304)      // ~97KB -> 2 CTAs/SM

__global__ void __launch_bounds__(256, 2) k_mma(const float* __restrict__ Z,
                                                const int* __restrict__ row) {
    extern __shared__ char smem[];
    float* attbuf = (float*)(smem + SM_ATT);
    int* rs = (int*)(smem + SM_ROW);
    const int tid = threadIdx.x;
    const int lane = tid & 31, wid = tid >> 5;
    const int warpM = wid & 3, warpN = wid >> 2;      // 4M x 2N
    const int m_base = warpM * 32, n_base = warpN * 64;
    const int e0 = blockIdx.x * 128;

    const uint32_t zbase = smem_u32(smem + SM_Z);
    const uint32_t wbase[2] = { smem_u32(smem + SM_W0), smem_u32(smem + SM_W1) };

    if (tid < 128) rs[tid] = row[e0 + tid];

    // ---- Z tile: 128x128 -> fp16, swizzled ----
#pragma unroll
    for (int it = 0; it < 16; it++) {
        int i = it * 256 + tid;
        int r = i >> 5, c4 = (i & 31) * 4;
        float4 v = *(const float4*)&Z[(size_t)(e0 + r) * D + c4];
        __half2 lo = __floats2half2_rn(v.x, v.y);
        __half2 hi = __floats2half2_rn(v.z, v.w);
        uint2 w = { *(uint32_t*)&lo, *(uint32_t*)&hi };
        *(uint2*)(smem + SM_Z + htile_off(r, c4)) = w;
    }

    // ---- prefetch W n-tile 0 ----
#pragma unroll
    for (int it = 0; it < 8; it++) {
        int i = it * 256 + tid;
        int r = i >> 4, ch = i & 15;
        CP_ASYNC16(wbase[0] + r * 256 + (uint32_t)((ch ^ (r & 7)) << 4),
                   &g_WcombH[(size_t)r * D + ch * 8]);
    }
    CP_COMMIT();

    const int l16 = lane & 15;
    const int khi = lane >> 4;
    uint32_t arow[2], aswz[2];
#pragma unroll
    for (int f = 0; f < 2; f++) {
        int r = m_base + f * 16 + l16;
        arow[f] = (uint32_t)r * 256;
        aswz[f] = (uint32_t)(r & 7);
    }
    uint32_t brow[4], bswz[4];
#pragma unroll
    for (int q = 0; q < 4; q++) {
        int r = n_base + q * 16 + l16;
        brow[q] = (uint32_t)r * 256;
        bswz[q] = (uint32_t)(r & 7);
    }

    const int crow = m_base + (lane >> 2);
    const int ccol = n_base + (lane & 3) * 2;

    for (int nt = 0; nt < 8; nt++) {
        const int buf = nt & 1;
        CP_WAIT0();
        __syncthreads();
        if (nt < 7) {
#pragma unroll
            for (int it = 0; it < 8; it++) {
                int i = it * 256 + tid;
                int r = i >> 4, ch = i & 15;
                CP_ASYNC16(wbase[buf ^ 1] + r * 256 + (uint32_t)((ch ^ (r & 7)) << 4),
                           &g_WcombH[(size_t)(nt + 1) * 128 * D + (size_t)r * D + ch * 8]);
            }
            CP_COMMIT();
        }

        float acc[2][8][4];
#pragma unroll
        for (int f = 0; f < 2; f++)
#pragma unroll
            for (int j = 0; j < 8; j++)
#pragma unroll
                for (int r = 0; r < 4; r++) acc[f][j][r] = 0.f;

        const uint32_t wb = wbase[buf];
#pragma unroll
        for (int ks = 0; ks < 8; ks++) {
            const uint32_t kc = (uint32_t)(ks * 2 + khi);
            uint32_t afr[2][4];
#pragma unroll
            for (int f = 0; f < 2; f++)
                ldsm4(afr[f], zbase + arow[f] + ((kc ^ aswz[f]) << 4));
            uint32_t bfr[8][2];
#pragma unroll
            for (int q = 0; q < 4; q++) {
                uint32_t t4[4];
                ldsm4(t4, wb + brow[q] + ((kc ^ bswz[q]) << 4));
                bfr[2 * q][0] = t4[0]; bfr[2 * q][1] = t4[2];
                bfr[2 * q + 1][0] = t4[1]; bfr[2 * q + 1][1] = t4[3];
            }
#pragma unroll
            for (int f = 0; f < 2; f++)
#pragma unroll
                for (int j = 0; j < 8; j++)
                    mma_f16(acc[f][j], afr[f], bfr[j]);
        }

        if (nt < 4) {
            // ---- fused att epilogue + segment max (head = nt) ----
            if (tid < 128) attbuf[tid] = 0.f;
            __syncthreads();
            float part[2][2] = {{0.f, 0.f}, {0.f, 0.f}};
#pragma unroll
            for (int f = 0; f < 2; f++)
#pragma unroll
                for (int j = 0; j < 8; j++) {
                    int col = ccol + j * 8;
#pragma unroll
                    for (int r8 = 0; r8 < 2; r8++) {
                        int rr = crow + f * 16 + r8 * 8;
                        __half2 zh = *(const __half2*)(smem + SM_Z + htile_off(rr, col));
                        float2 z = __half22float2(zh);
                        part[f][r8] += acc[f][j][r8 * 2] * z.x + acc[f][j][r8 * 2 + 1] * z.y;
                    }
                }
#pragma unroll
            for (int f = 0; f < 2; f++)
#pragma unroll
                for (int r8 = 0; r8 < 2; r8++) {
                    float p = part[f][r8];
                    p += __shfl_xor_sync(0xFFFFFFFFu, p, 1);
                    p += __shfl_xor_sync(0xFFFFFFFFu, p, 2);
                    if ((lane & 3) == 0)
                        atomicAdd(&attbuf[crow + f * 16 + r8 * 8], p);
                }
            __syncthreads();
            if (tid < 128) {
                float v = 0.08838834764831845f * attbuf[tid];
                g_att[(size_t)(e0 + tid) * H + nt] = v;
                atomicMax(&g_m[rs[tid] * H + nt], encodeF(v));
            }
        } else {
            // ---- p-half store (fp16) ----
            const int colb = (nt - 4) * 128 + ccol;
#pragma unroll
            for (int f = 0; f < 2; f++) {
                int r0 = crow + f * 16;
#pragma unroll
                for (int j = 0; j < 8; j++) {
                    __half2 v0 = __floats2half2_rn(acc[f][j][0], acc[f][j][1]);
                    __half2 v1 = __floats2half2_rn(acc[f][j][2], acc[f][j][3]);
                    *(__half2*)&g_Yh[(size_t)(e0 + r0) * PHALF + colb + j * 8] = v0;
                    *(__half2*)&g_Yh[(size_t)(e0 + r0 + 8) * PHALF + colb + j * 8] = v1;
                }
            }
        }
    }
}

// ---------------- K4: exp + segment sum ------------------------------------
__global__ void k_exp(const int* __restrict__ row) {
    int i = blockIdx.x * 256 + threadIdx.x;
    if (i >= E_EDGES * H) return;
    int e = i >> 2, h = i & 3;
    int rw = row[e];
    float m = decodeF(g_m[rw * H + h]);
    float ev = __expf(g_att[i] - m);
    g_att[i] = ev;
    atomicAdd(&g_s[rw * H + h], ev);
}

// ---------------- K5: final, 128-edge tiles, 256 thr, vectorized combine ---
#define SMF_WS  0                 // 512 floats = 2KB
#define SMF_B1  2048
#define SMF_B2  2560
#define SMF_H1  4096              // 128 rows * 256B = 32KB
#define SMF_W2  (4096 + 32768)    // 128 rows * 256B = 32KB
#define SMEMF_SZ (4096 + 65536)   // 68KB -> 2 CTAs/SM

__global__ void __launch_bounds__(256, 2) k_final(const int* __restrict__ row,
                                                  const float* __restrict__ b1,
                                                  const float* __restrict__ b2,
                                                  float* __restrict__ out) {
    extern __shared__ char smem[];
    float* ws  = (float*)(smem + SMF_WS);    // [128][4]
    float* b1s = (float*)(smem + SMF_B1);
    float* b2s = (float*)(smem + SMF_B2);
    const int tid = threadIdx.x;
    const int lane = tid & 31, wid = tid >> 5;   // 8 warps
    const int e0 = blockIdx.x * 128;
    const uint32_t h1base = smem_u32(smem + SMF_H1);
    const uint32_t w2base = smem_u32(smem + SMF_W2);

    // prefetch W2 tile (fp16, 128 rows)
#pragma unroll
    for (int it = 0; it < 8; it++) {
        int i = it * 256 + tid;
        int r = i >> 4, ch = i & 15;
        CP_ASYNC16(w2base + r * 256 + (uint32_t)((ch ^ (r & 7)) << 4),
                   &g_W2H[(size_t)r * D + ch * 8]);
    }
    CP_COMMIT();

    if (tid < 128) { b1s[tid] = b1[tid]; b2s[tid] = b2[tid]; }
#pragma unroll
    for (int it = 0; it < 2; it++) {
        int idx = it * 256 + tid;
        int e = e0 + (idx >> 2), h = idx & 3;
        ws[idx] = g_att[(size_t)e * H + h] / g_s[row[e] * H + h];
    }
    __syncthreads();

    // h1 = SiLU(sum_h w*p + b1) -> fp16 swizzled smem.
    // Vectorized: one thread = 8 consecutive features of one edge;
    // 4 x uint4 coalesced loads (one per head row).
#pragma unroll
    for (int it = 0; it < 8; it++) {
        int idx = it * 256 + tid;               // 2048 items
        int m = idx >> 4, c0 = (idx & 15) * 8;
        const uint4* yp = (const uint4*)(g_Yh + (size_t)(e0 + m) * PHALF + c0);
        const float4 w4 = *(const float4*)&ws[m * 4];
        uint32_t y0[4], y1[4], y2[4], y3[4];
        *(uint4*)y0 = yp[0];
        *(uint4*)y1 = yp[16];     // +128 halfs
        *(uint4*)y2 = yp[32];
        *(uint4*)y3 = yp[48];
        uint32_t outp[4];
#pragma unroll
        for (int p = 0; p < 4; p++) {
            float2 f0 = __half22float2(*(__half2*)&y0[p]);
            float2 f1 = __half22float2(*(__half2*)&y1[p]);
            float2 f2 = __half22float2(*(__half2*)&y2[p]);
            float2 f3 = __half22float2(*(__half2*)&y3[p]);
            float px = b1s[c0 + 2 * p]     + w4.x * f0.x + w4.y * f1.x + w4.z * f2.x + w4.w * f3.x;
            float py = b1s[c0 + 2 * p + 1] + w4.x * f0.y + w4.y * f1.y + w4.z * f2.y + w4.w * f3.y;
            float hx = px / (1.f + __expf(-px));
            float hy = py / (1.f + __expf(-py));
            __half2 hh = __floats2half2_rn(hx, hy);
            outp[p] = *(uint32_t*)&hh;
        }
        *(uint4*)(smem + SMF_H1 + htile_off(m, c0)) = *(uint4*)outp;
    }
    CP_WAIT0();
    __syncthreads();

    // mma: out = h1(128x128) @ W2^T (same engine as k_mma)
    const int warpM = wid & 3, warpN = wid >> 2;      // 4M x 2N
    const int m_base = warpM * 32, n_base = warpN * 64;
    const int l16 = lane & 15;
    const int khi = lane >> 4;
    uint32_t arow[2], aswz[2];
#pragma unroll
    for (int f = 0; f < 2; f++) {
        int r = m_base + f * 16 + l16;
        arow[f] = (uint32_t)r * 256;
        aswz[f] = (uint32_t)(r & 7);
    }
    uint32_t brow[4], bswz[4];
#pragma unroll
    for (int q = 0; q < 4; q++) {
        int r = n_base + q * 16 + l16;
        brow[q] = (uint32_t)r * 256;
        bswz[q] = (uint32_t)(r & 7);
    }

    float acc[2][8][4];
#pragma unroll
    for (int f = 0; f < 2; f++)
#pragma unroll
        for (int j = 0; j < 8; j++)
#pragma unroll
            for (int r = 0; r < 4; r++) acc[f][j][r] = 0.f;

#pragma unroll
    for (int ks = 0; ks < 8; ks++) {
        const uint32_t kc = (uint32_t)(ks * 2 + khi);
        uint32_t afr[2][4];
#pragma unroll
        for (int f = 0; f < 2; f++)
            ldsm4(afr[f], h1base + arow[f] + ((kc ^ aswz[f]) << 4));
        uint32_t bfr[8][2];
#pragma unroll
        for (int q = 0; q < 4; q++) {
            uint32_t t4[4];
            ldsm4(t4, w2base + brow[q] + ((kc ^ bswz[q]) << 4));
            bfr[2 * q][0] = t4[0]; bfr[2 * q][1] = t4[2];
            bfr[2 * q + 1][0] = t4[1]; bfr[2 * q + 1][1] = t4[3];
        }
#pragma unroll
        for (int f = 0; f < 2; f++)
#pragma unroll
            for (int j = 0; j < 8; j++)
                mma_f16(acc[f][j], afr[f], bfr[j]);
    }

    const int crow = m_base + (lane >> 2);
    const int ccol = n_base + (lane & 3) * 2;
#pragma unroll
    for (int f = 0; f < 2; f++) {
        int r0 = e0 + crow + f * 16;
#pragma unroll
        for (int j = 0; j < 8; j++) {
            int col = ccol + j * 8;
            float bx = b2s[col], by = b2s[col + 1];
            *(float2*)&out[(size_t)r0 * D + col] =
                make_float2(acc[f][j][0] + bx, acc[f][j][1] + by);
            *(float2*)&out[(size_t)(r0 + 8) * D + col] =
                make_float2(acc[f][j][2] + bx, acc[f][j][3] + by);
        }
    }
}

// ---------------- launch ----------------------------------------------------
extern "C" void kernel_launch(void* const* d_in, const int* in_sizes, int n_in,
                              void* d_out, int out_size) {
    const float* Z     = (const float*)d_in[0];
    const int*   edges = (const int*)  d_in[1];
    const float* Wq    = (const float*)d_in[2];
    const float* Wk    = (const float*)d_in[3];
    const float* Wv    = (const float*)d_in[4];
    const float* W1    = (const float*)d_in[5];
    const float* b1    = (const float*)d_in[6];
    const float* W2    = (const float*)d_in[7];
    const float* b2    = (const float*)d_in[8];
    float* out = (float*)d_out;
    const int* row = edges;

    cudaFuncSetAttribute(k_mma, cudaFuncAttributeMaxDynamicSharedMemorySize, SMEM_SZ);
    cudaFuncSetAttribute(k_final, cudaFuncAttributeMaxDynamicSharedMemorySize, SMEMF_SZ);

    k_build<<<NCOMB + D, D>>>(Wq, Wk, Wv, W1, W2);
    k_init<<<(N_NODES * H + 255) / 256, 256>>>();
    k_nop<<<1, 1>>>();   // aligns ncu capture onto k_mma
    k_mma<<<E_EDGES / 128, 256, SMEM_SZ>>>(Z, row);
    k_exp<<<(E_EDGES * H + 255) / 256, 256>>>(row);
    k_final<<<E_EDGES / 128, 256, SMEMF_SZ>>>(row, b1, b2, out);
}